// round 15
// baseline (speedup 1.0000x reference)
#include <cuda_runtime.h>
#include <cuda_fp16.h>
#include <cstdint>

// ---------------- problem constants ----------------
#define BB   8
#define CCH  256
#define HH   64
#define WW   96
#define ND   21
#define NDD  441
#define HW_  6144            // HH*WW

// ---------------- prepared layouts ----------------
// g_B: fp16 swizzled parity image per (b,y): row r in [0,96): parity p=r/48,
//      u=r%48, x=2u+p; element (r, ku) at r*512 + ((ku ^ (r&7))*16) + (k&7)*2.
// g_A: A fragments in per-thread ldsm-order: per (b,y):
//      [(par*3+mt)*2+kh][ks*32+lane] -> uint4 = a[ks][0..3]
#define IMG_SZ 49152         // both: 49152 B per (b,y)
#define HALF_SZ 24576

__device__ __align__(16) unsigned char g_A[(size_t)BB * HH * IMG_SZ];
__device__ __align__(16) unsigned char g_B[(size_t)BB * HH * IMG_SZ];

// ---------------- main-kernel smem (relative to 1024-aligned base) ----------
#define SM_RED  49152        // trimmed split-K scratch: 7168 B
#define SMEM_REQ (56320 + 1024)   // 57344 = 56 KB -> 4 CTAs/SM

// ---------------- ptx helpers (baseline PTX only) -------
__device__ __forceinline__ void cp_async16(uint32_t s, const void* g) {
    asm volatile("cp.async.cg.shared.global [%0], [%1], 16;\n" :: "r"(s), "l"(g));
}
__device__ __forceinline__ void cp_commit() {
    asm volatile("cp.async.commit_group;" ::: "memory");
}
template<int N> __device__ __forceinline__ void cp_wait() {
    asm volatile("cp.async.wait_group %0;" :: "n"(N) : "memory");
}
__device__ __forceinline__ void ldsm4(uint32_t* r, uint32_t a) {
    asm volatile("ldmatrix.sync.aligned.m8n8.x4.shared.b16 {%0,%1,%2,%3}, [%4];"
                 : "=r"(r[0]), "=r"(r[1]), "=r"(r[2]), "=r"(r[3]) : "r"(a));
}
__device__ __forceinline__ void mma16816(float* d, const uint32_t* a, const uint32_t* b) {
    asm volatile("mma.sync.aligned.m16n8k16.row.col.f32.f16.f16.f32 "
                 "{%0,%1,%2,%3}, {%4,%5,%6,%7}, {%8,%9}, {%0,%1,%2,%3};"
                 : "+f"(d[0]), "+f"(d[1]), "+f"(d[2]), "+f"(d[3])
                 : "r"(a[0]), "r"(a[1]), "r"(a[2]), "r"(a[3]), "r"(b[0]), "r"(b[1]));
}

// ================= prepass =====================================================
// bid < 2048: A fragments for (b,y,q-chunk).  bid >= 2048: B image chunk.
__global__ __launch_bounds__(256) void prep_img(const float* __restrict__ in1,
                                                const float* __restrict__ in2) {
    __shared__ float raw[64][97];
    int bid = blockIdx.x;
    int q = bid & 3;                 // channel chunk q*64 .. q*64+63
    int sb = (bid >> 2) & 511;       // (b, y)
    bool isB = bid >= 2048;
    int y = sb & 63, b = sb >> 6;
    int tid = threadIdx.x, w = tid >> 5, lane = tid & 31;
    const float* src_t = isB ? in2 : in1;

    #pragma unroll
    for (int rr = 0; rr < 8; rr++) {
        int c = w * 8 + rr;
        const float* src = src_t + (((size_t)b * CCH + q * 64 + c) * HH + y) * WW;
        #pragma unroll
        for (int m = 0; m < 3; m++)
            raw[c][lane + 32 * m] = src[lane + 32 * m];
    }
    __syncthreads();

    if (isB) {
        unsigned char* img = g_B + (size_t)sb * IMG_SZ;
        #pragma unroll
        for (int it = 0; it < 3; it++) {
            int u = tid + it * 256;              // u < 768: 96 rows * 8 k-units
            int r = u >> 3, kl = u & 7;
            int ku = q * 8 + kl;
            int x = (r < 48) ? (2 * r) : (2 * r - 95);   // parity-split mapping
            uint32_t h[4];
            #pragma unroll
            for (int j = 0; j < 4; j++) {
                __half2 v = __floats2half2_rn(raw[kl * 8 + 2 * j][x],
                                              raw[kl * 8 + 2 * j + 1][x]);
                h[j] = *reinterpret_cast<uint32_t*>(&v);
            }
            int off = r * 512 + ((ku ^ (r & 7)) << 4);
            *reinterpret_cast<uint4*>(img + off) = make_uint4(h[0], h[1], h[2], h[3]);
        }
    } else {
        // A fragments. This q covers global k-steps gks = (q&1)*4 + ksl, kh = q>>1.
        unsigned char* dstb = g_A + (size_t)sb * IMG_SZ;
        int kh = q >> 1;
        #pragma unroll
        for (int it = 0; it < 3; it++) {
            int u = tid + it * 256;              // u < 768
            int par = u / 384;
            int rem = u - par * 384;
            int mt = rem >> 7;                   // 0..2
            int rem2 = rem & 127;
            int ksl = rem2 >> 5, ln = rem2 & 31;
            int gks = (q & 1) * 4 + ksl;
            uint32_t h[4];
            #pragma unroll
            for (int j = 0; j < 4; j++) {
                int kl = 2 * ksl + (j >> 1);
                int c = kl * 8 + 2 * (ln & 3);
                int x = 2 * (16 * mt + 8 * (j & 1) + (ln >> 2)) + par;
                __half2 v = __floats2half2_rn(raw[c][x], raw[c + 1][x]);
                h[j] = *reinterpret_cast<uint32_t*>(&v);
            }
            int off = ((par * 3 + mt) * 2 + kh) * 4096 + (gks * 32 + ln) * 16;
            *reinterpret_cast<uint4*>(dstb + off) = make_uint4(h[0], h[1], h[2], h[3]);
        }
    }
}

// ================= main kernel ================================================
// Block = (b, y, parity). 6 warps = 3 m16 tiles x 2 k-halves. A fragments
// loaded straight from global (no smem A). smem = 2 B slots + 7 KB reduce
// scratch = 56 KB -> 4 co-resident CTAs/SM (24 warps).
__global__ __launch_bounds__(192, 4) void corr_hmma(float* __restrict__ out) {
    extern __shared__ __align__(16) unsigned char smraw[];
    uint32_t SB = ((uint32_t)__cvta_generic_to_shared(smraw) + 1023u) & ~1023u;

    int bid = blockIdx.x;
    int par = bid & 1;
    int y = (bid >> 1) & 63;
    int b = bid >> 7;
    int tid = threadIdx.x, w = tid >> 5, lane = tid & 31;
    int mt = w % 3;          // m16 tile within parity half
    int kh = w / 3;          // k-half
    int lg = lane >> 2, t = lane & 3;
    int l7 = lane & 7;

    // ---- staging: B parity half (24 KB) -> slot d&1 (empty if invalid) ----
    auto stage = [&](int d) {
        int y2 = y - 20 + 2 * d;
        if ((unsigned)y2 < (unsigned)HH) {
            const unsigned char* src = g_B + (size_t)(b * HH + y2) * IMG_SZ
                                     + (size_t)(par * HALF_SZ);
            uint32_t dst = SB + (uint32_t)((d & 1) * HALF_SZ);
            #pragma unroll
            for (int it = 0; it < 8; it++) {
                int i = tid + it * 192;          // i < 1536
                cp_async16(dst + (uint32_t)(i * 16), src + (size_t)i * 16);
            }
        }
    };

    // ---- prologue: B(0) (G0), B(1) (G1); A fragments via plain LDG ----
    stage(0);
    cp_commit();
    stage(1);
    cp_commit();

    uint32_t a[8][4];
    {
        const unsigned char* af = g_A + (size_t)(b * HH + y) * IMG_SZ
                                + (size_t)(((par * 3 + mt) * 2 + kh) * 4096);
        #pragma unroll
        for (int ks = 0; ks < 8; ks++) {
            uint4 v = *reinterpret_cast<const uint4*>(af + (ks * 32 + lane) * 16);
            a[ks][0] = v.x; a[ks][1] = v.y; a[ks][2] = v.z; a[ks][3] = v.w;
        }
    }

    // ---- zero invalid-dy output slices (this parity's x positions only) ----
    #pragma unroll 1
    for (int d = 0; d < ND; d++) {
        int y2 = y - 20 + 2 * d;
        if ((unsigned)y2 >= (unsigned)HH) {
            for (int i = tid; i < ND * 48; i += 192) {
                int dj = i / 48, xh = i - dj * 48;
                out[(((size_t)b * NDD + d * ND + dj) * HH + y) * WW + 2 * xh + par] = 0.0f;
            }
        }
    }

    // ---- B ldsm local row offsets: q covers tiles jj = 2q, 2q+1 ----
    // valid pairs: mt=0 -> q 1..2, mt=1 -> q 0..2, mt=2 -> q 0..1
    int qlo = (mt == 0) ? 1 : 0;
    int qhi = (mt == 2) ? 1 : 2;
    int boff[3];
    #pragma unroll
    for (int q = 0; q < 3; q++) {
        int row = 8 * (2 * mt + 2 * q + (lane >> 4)) - 16 + l7;
        if (q < qlo || q > qhi) row = 0;         // unused; keep address sane
        boff[q] = row * 512;
    }
    uint32_t kadd = (uint32_t)((lane >> 3) & 1);
    // trimmed reduce scratch: mt0 -> 4 tiles @0, mt1 -> 6 @2048, mt2 -> 4 @5120
    uint32_t redslot = SB + SM_RED + (uint32_t)((mt == 0) ? 0 : (mt == 1 ? 2048 : 5120));
    const float scale = 1.0f / 256.0f;

    // ---- pipeline over all 21 dy (invalid iters: barriers only) ----
    #pragma unroll 1
    for (int d = 0; d < ND; d++) {
        cp_wait<1>();
        __syncthreads();                         // B(d) visible (if valid)

        bool valid = (unsigned)(y - 20 + 2 * d) < (unsigned)HH;
        uint32_t slot = SB + (uint32_t)((d & 1) * HALF_SZ);

        float acc[6][4];
        #pragma unroll
        for (int jj = 0; jj < 6; jj++)
            #pragma unroll
            for (int r = 0; r < 4; r++) acc[jj][r] = 0.0f;

        if (valid) {
            #pragma unroll
            for (int ks = 0; ks < 8; ks++) {
                uint32_t sw = (((uint32_t)(kh * 16 + 2 * ks) + kadd) ^ (uint32_t)l7) << 4;
                #pragma unroll
                for (int q = 0; q < 3; q++) {
                    if (q >= qlo && q <= qhi) {
                        uint32_t bfr[2][2];
                        ldsm4(&bfr[0][0], slot + (uint32_t)boff[q] + sw);
                        mma16816(acc[2 * q],     a[ks], bfr[0]);
                        mma16816(acc[2 * q + 1], a[ks], bfr[1]);
                    }
                }
            }
            // kh=0 publishes valid-tile partials
            if (kh == 0) {
                #pragma unroll
                for (int q = 0; q < 3; q++) {
                    if (q >= qlo && q <= qhi) {
                        #pragma unroll
                        for (int jl = 0; jl < 2; jl++)
                            #pragma unroll
                            for (int r = 0; r < 4; r++) {
                                int idx = (2 * (q - qlo) + jl) * 4 + r;
                                asm volatile("st.shared.f32 [%0], %1;"
                                    :: "r"(redslot + (uint32_t)((idx * 32 + lane) * 4)),
                                       "f"(acc[2 * q + jl][r]) : "memory");
                            }
                    }
                }
            }
        }
        __syncthreads();                         // partials visible; B reads done
        if (d + 2 < ND) stage(d + 2);
        cp_commit();                             // one group per iter (maybe empty)

        // kh=1 reduces + writes the band (overlaps staging)
        if (valid && kh == 1) {
            size_t obase = ((size_t)(b * NDD + d * ND)) * HW_ + (size_t)y * WW;
            #pragma unroll
            for (int q = 0; q < 3; q++) {
                if (q >= qlo && q <= qhi) {
                    #pragma unroll
                    for (int jl = 0; jl < 2; jl++) {
                        int jj = 2 * q + jl;
                        #pragma unroll
                        for (int r = 0; r < 4; r++) {
                            int idx = (2 * (q - qlo) + jl) * 4 + r;
                            float p;
                            asm volatile("ld.shared.f32 %0, [%1];"
                                : "=f"(p)
                                : "r"(redslot + (uint32_t)((idx * 32 + lane) * 4)));
                            float v = acc[jj][r] + p;
                            int rh = r >> 1;
                            int dxj = 8 * jj + 2 * t + (r & 1) - lg - 8 * rh - 6;
                            int x = 32 * mt + 2 * lg + 16 * rh + par;
                            if ((unsigned)dxj <= 20u)
                                out[obase + (size_t)dxj * HW_ + x] = v * scale;
                        }
                    }
                }
            }
        }
    }
}

// ================= launch =================
extern "C" void kernel_launch(void* const* d_in, const int* in_sizes, int n_in,
                              void* d_out, int out_size)
{
    const float* in1 = (const float*)d_in[0];
    const float* in2 = (const float*)d_in[1];
    float* out = (float*)d_out;

    cudaFuncSetAttribute(corr_hmma, cudaFuncAttributeMaxDynamicSharedMemorySize, SMEM_REQ);

    prep_img<<<4096, 256>>>(in1, in2);
    corr_hmma<<<BB * HH * 2, 192, SMEM_REQ>>>(out);
}

// round 16
// speedup vs baseline: 1.1225x; 1.1225x over previous
#include <cuda_runtime.h>
#include <cuda_fp16.h>
#include <cstdint>

// ---------------- problem constants ----------------
#define BB   8
#define CCH  256
#define HH   64
#define WW   96
#define ND   21
#define NDD  441
#define HW_  6144            // HH*WW

// ---------------- prepared layouts ----------------
// g_B: fp16 swizzled parity image per (b,y): row r in [0,96): parity p=r/48,
//      u=r%48, x=2u+p; element (r, ku) at r*512 + ((ku ^ (r&7))*16) + (k&7)*2.
// g_A: A fragments in per-thread ldsm-order: per (b,y):
//      [(par*3+mt)*2+kh][ks*32+lane] -> uint4 = a[ks][0..3]
#define IMG_SZ 49152         // both: 49152 B per (b,y)
#define HALF_SZ 24576

__device__ __align__(16) unsigned char g_A[(size_t)BB * HH * IMG_SZ];
__device__ __align__(16) unsigned char g_B[(size_t)BB * HH * IMG_SZ];

// ---------------- main-kernel smem (relative to 1024-aligned base) ----------
#define SM_RED  49152        // trimmed split-K scratch: 7168 B
#define SMEM_REQ (56320 + 1024)   // 57344 = 56 KB -> 4 CTAs/SM

// ---------------- ptx helpers (baseline PTX only) -------
__device__ __forceinline__ void cp_async16(uint32_t s, const void* g) {
    asm volatile("cp.async.cg.shared.global [%0], [%1], 16;\n" :: "r"(s), "l"(g));
}
__device__ __forceinline__ void cp_commit() {
    asm volatile("cp.async.commit_group;" ::: "memory");
}
template<int N> __device__ __forceinline__ void cp_wait() {
    asm volatile("cp.async.wait_group %0;" :: "n"(N) : "memory");
}
__device__ __forceinline__ void ldsm4(uint32_t* r, uint32_t a) {
    asm volatile("ldmatrix.sync.aligned.m8n8.x4.shared.b16 {%0,%1,%2,%3}, [%4];"
                 : "=r"(r[0]), "=r"(r[1]), "=r"(r[2]), "=r"(r[3]) : "r"(a));
}
__device__ __forceinline__ void mma16816(float* d, const uint32_t* a, const uint32_t* b) {
    asm volatile("mma.sync.aligned.m16n8k16.row.col.f32.f16.f16.f32 "
                 "{%0,%1,%2,%3}, {%4,%5,%6,%7}, {%8,%9}, {%0,%1,%2,%3};"
                 : "+f"(d[0]), "+f"(d[1]), "+f"(d[2]), "+f"(d[3])
                 : "r"(a[0]), "r"(a[1]), "r"(a[2]), "r"(a[3]), "r"(b[0]), "r"(b[1]));
}

// ================= prepass =====================================================
// bid < 2048: A fragments for (b,y,q-chunk).  bid >= 2048: B image chunk.
__global__ __launch_bounds__(256) void prep_img(const float* __restrict__ in1,
                                                const float* __restrict__ in2) {
    __shared__ float raw[64][97];
    int bid = blockIdx.x;
    int q = bid & 3;                 // channel chunk q*64 .. q*64+63
    int sb = (bid >> 2) & 511;       // (b, y)
    bool isB = bid >= 2048;
    int y = sb & 63, b = sb >> 6;
    int tid = threadIdx.x, w = tid >> 5, lane = tid & 31;
    const float* src_t = isB ? in2 : in1;

    if (lane < 24) {
        #pragma unroll
        for (int rr = 0; rr < 8; rr++) {
            int c = w * 8 + rr;
            const float* src = src_t + (((size_t)b * CCH + q * 64 + c) * HH + y) * WW;
            float4 v = *reinterpret_cast<const float4*>(src + lane * 4);
            raw[c][lane * 4 + 0] = v.x;
            raw[c][lane * 4 + 1] = v.y;
            raw[c][lane * 4 + 2] = v.z;
            raw[c][lane * 4 + 3] = v.w;
        }
    }
    __syncthreads();

    if (isB) {
        unsigned char* img = g_B + (size_t)sb * IMG_SZ;
        #pragma unroll
        for (int it = 0; it < 3; it++) {
            int u = tid + it * 256;              // u < 768: 96 rows * 8 k-units
            int r = u >> 3, kl = u & 7;
            int ku = q * 8 + kl;
            int x = (r < 48) ? (2 * r) : (2 * r - 95);   // parity-split mapping
            uint32_t h[4];
            #pragma unroll
            for (int j = 0; j < 4; j++) {
                __half2 v = __floats2half2_rn(raw[kl * 8 + 2 * j][x],
                                              raw[kl * 8 + 2 * j + 1][x]);
                h[j] = *reinterpret_cast<uint32_t*>(&v);
            }
            int off = r * 512 + ((ku ^ (r & 7)) << 4);
            *reinterpret_cast<uint4*>(img + off) = make_uint4(h[0], h[1], h[2], h[3]);
        }
    } else {
        // A fragments. This q covers global k-steps gks = (q&1)*4 + ksl, kh = q>>1.
        unsigned char* dstb = g_A + (size_t)sb * IMG_SZ;
        int kh = q >> 1;
        #pragma unroll
        for (int it = 0; it < 3; it++) {
            int u = tid + it * 256;              // u < 768
            int par = u / 384;
            int rem = u - par * 384;
            int mt = rem >> 7;                   // 0..2
            int rem2 = rem & 127;
            int ksl = rem2 >> 5, ln = rem2 & 31;
            int gks = (q & 1) * 4 + ksl;
            uint32_t h[4];
            #pragma unroll
            for (int j = 0; j < 4; j++) {
                int kl = 2 * ksl + (j >> 1);
                int c = kl * 8 + 2 * (ln & 3);
                int x = 2 * (16 * mt + 8 * (j & 1) + (ln >> 2)) + par;
                __half2 v = __floats2half2_rn(raw[c][x], raw[c + 1][x]);
                h[j] = *reinterpret_cast<uint32_t*>(&v);
            }
            int off = ((par * 3 + mt) * 2 + kh) * 4096 + (gks * 32 + ln) * 16;
            *reinterpret_cast<uint4*>(dstb + off) = make_uint4(h[0], h[1], h[2], h[3]);
        }
    }
}

// ================= main kernel ================================================
// Block = (b, y, parity). 6 warps = 3 m16 tiles x 2 k-halves. A fragments
// streamed per-ks from global (L1-resident after first dy) -> low reg
// pressure, no spills. smem 56 KB -> 4 co-resident CTAs/SM (24 warps).
__global__ __launch_bounds__(192, 4) void corr_hmma(float* __restrict__ out) {
    extern __shared__ __align__(16) unsigned char smraw[];
    uint32_t SB = ((uint32_t)__cvta_generic_to_shared(smraw) + 1023u) & ~1023u;

    int bid = blockIdx.x;
    int par = bid & 1;
    int y = (bid >> 1) & 63;
    int b = bid >> 7;
    int tid = threadIdx.x, w = tid >> 5, lane = tid & 31;
    int mt = w % 3;          // m16 tile within parity half
    int kh = w / 3;          // k-half
    int lg = lane >> 2, t = lane & 3;
    int l7 = lane & 7;

    // ---- staging: B parity half (24 KB) -> slot d&1 (empty if invalid) ----
    auto stage = [&](int d) {
        int y2 = y - 20 + 2 * d;
        if ((unsigned)y2 < (unsigned)HH) {
            const unsigned char* src = g_B + (size_t)(b * HH + y2) * IMG_SZ
                                     + (size_t)(par * HALF_SZ);
            uint32_t dst = SB + (uint32_t)((d & 1) * HALF_SZ);
            #pragma unroll
            for (int it = 0; it < 8; it++) {
                int i = tid + it * 192;          // i < 1536
                cp_async16(dst + (uint32_t)(i * 16), src + (size_t)i * 16);
            }
        }
    };

    // ---- prologue: B(0) (G0), B(1) (G1) ----
    stage(0);
    cp_commit();
    stage(1);
    cp_commit();

    // per-warp A fragment base (LDG.128 per ks inside the loop)
    const unsigned char* af = g_A + (size_t)(b * HH + y) * IMG_SZ
                            + (size_t)(((par * 3 + mt) * 2 + kh) * 4096)
                            + (size_t)(lane * 16);

    // ---- zero invalid-dy output slices (this parity's x positions only) ----
    #pragma unroll 1
    for (int d = 0; d < ND; d++) {
        int y2 = y - 20 + 2 * d;
        if ((unsigned)y2 >= (unsigned)HH) {
            for (int i = tid; i < ND * 48; i += 192) {
                int dj = i / 48, xh = i - dj * 48;
                out[(((size_t)b * NDD + d * ND + dj) * HH + y) * WW + 2 * xh + par] = 0.0f;
            }
        }
    }

    // ---- B ldsm local row offsets: q covers tiles jj = 2q, 2q+1 ----
    // valid pairs: mt=0 -> q 1..2, mt=1 -> q 0..2, mt=2 -> q 0..1
    int qlo = (mt == 0) ? 1 : 0;
    int qhi = (mt == 2) ? 1 : 2;
    int boff[3];
    #pragma unroll
    for (int q = 0; q < 3; q++) {
        int row = 8 * (2 * mt + 2 * q + (lane >> 4)) - 16 + l7;
        if (q < qlo || q > qhi) row = 0;         // unused; keep address sane
        boff[q] = row * 512;
    }
    uint32_t kadd = (uint32_t)((lane >> 3) & 1);
    // trimmed reduce scratch: mt0 -> 4 tiles @0, mt1 -> 6 @2048, mt2 -> 4 @5120
    uint32_t redslot = SB + SM_RED + (uint32_t)((mt == 0) ? 0 : (mt == 1 ? 2048 : 5120));
    const float scale = 1.0f / 256.0f;

    // ---- pipeline over all 21 dy (invalid iters: barriers only) ----
    #pragma unroll 1
    for (int d = 0; d < ND; d++) {
        cp_wait<1>();
        __syncthreads();                         // B(d) visible (if valid)

        bool valid = (unsigned)(y - 20 + 2 * d) < (unsigned)HH;
        uint32_t slot = SB + (uint32_t)((d & 1) * HALF_SZ);

        float acc[6][4];
        #pragma unroll
        for (int jj = 0; jj < 6; jj++)
            #pragma unroll
            for (int r = 0; r < 4; r++) acc[jj][r] = 0.0f;

        if (valid) {
            #pragma unroll
            for (int ks = 0; ks < 8; ks++) {
                // A fragment for this ks: one L1-resident LDG.128, short-lived
                uint4 av = *reinterpret_cast<const uint4*>(af + (size_t)(ks * 512));
                uint32_t aa[4] = {av.x, av.y, av.z, av.w};

                uint32_t sw = (((uint32_t)(kh * 16 + 2 * ks) + kadd) ^ (uint32_t)l7) << 4;
                #pragma unroll
                for (int q = 0; q < 3; q++) {
                    if (q >= qlo && q <= qhi) {
                        uint32_t bfr[2][2];
                        ldsm4(&bfr[0][0], slot + (uint32_t)boff[q] + sw);
                        mma16816(acc[2 * q],     aa, bfr[0]);
                        mma16816(acc[2 * q + 1], aa, bfr[1]);
                    }
                }
            }
            // kh=0 publishes valid-tile partials
            if (kh == 0) {
                #pragma unroll
                for (int q = 0; q < 3; q++) {
                    if (q >= qlo && q <= qhi) {
                        #pragma unroll
                        for (int jl = 0; jl < 2; jl++)
                            #pragma unroll
                            for (int r = 0; r < 4; r++) {
                                int idx = (2 * (q - qlo) + jl) * 4 + r;
                                asm volatile("st.shared.f32 [%0], %1;"
                                    :: "r"(redslot + (uint32_t)((idx * 32 + lane) * 4)),
                                       "f"(acc[2 * q + jl][r]) : "memory");
                            }
                    }
                }
            }
        }
        __syncthreads();                         // partials visible; B reads done
        if (d + 2 < ND) stage(d + 2);
        cp_commit();                             // one group per iter (maybe empty)

        // kh=1 reduces + writes the band (overlaps staging)
        if (valid && kh == 1) {
            size_t obase = ((size_t)(b * NDD + d * ND)) * HW_ + (size_t)y * WW;
            #pragma unroll
            for (int q = 0; q < 3; q++) {
                if (q >= qlo && q <= qhi) {
                    #pragma unroll
                    for (int jl = 0; jl < 2; jl++) {
                        int jj = 2 * q + jl;
                        #pragma unroll
                        for (int r = 0; r < 4; r++) {
                            int idx = (2 * (q - qlo) + jl) * 4 + r;
                            float p;
                            asm volatile("ld.shared.f32 %0, [%1];"
                                : "=f"(p)
                                : "r"(redslot + (uint32_t)((idx * 32 + lane) * 4)));
                            float v = acc[jj][r] + p;
                            int rh = r >> 1;
                            int dxj = 8 * jj + 2 * t + (r & 1) - lg - 8 * rh - 6;
                            int x = 32 * mt + 2 * lg + 16 * rh + par;
                            if ((unsigned)dxj <= 20u)
                                out[obase + (size_t)dxj * HW_ + x] = v * scale;
                        }
                    }
                }
            }
        }
    }
}

// ================= launch =================
extern "C" void kernel_launch(void* const* d_in, const int* in_sizes, int n_in,
                              void* d_out, int out_size)
{
    const float* in1 = (const float*)d_in[0];
    const float* in2 = (const float*)d_in[1];
    float* out = (float*)d_out;

    cudaFuncSetAttribute(corr_hmma, cudaFuncAttributeMaxDynamicSharedMemorySize, SMEM_REQ);

    prep_img<<<4096, 256>>>(in1, in2);
    corr_hmma<<<BB * HH * 2, 192, SMEM_REQ>>>(out);
}